// round 12
// baseline (speedup 1.0000x reference)
#include <cuda_runtime.h>

#define NJ 24
#define NV 6890
#define JSPLIT 54
#define JCHUNK 128   // 54*128 = 6912 >= 6890

__device__ __constant__ int c_par[NJ] =
    {-1,0,0,0,1,2,3,4,5,6,7,8,9,9,9,12,13,14,16,17,18,19,20,21};

typedef unsigned long long u64;

// scratch (no allocations allowed -> __device__ globals)
__device__ float g_part[NJ][JSPLIT][6];  // per-(joint,slice) partial sums
__device__ float g_A[NJ * 12];           // per joint: 3x4 row-major blend matrix

// ---------------------------------------------------------------------------
// Kernel 1: partial joint sums.  grid = (JSPLIT, NJ), block = 128.
// shapedirs/v_template staged through smem with coalesced float4 loads.
// ---------------------------------------------------------------------------
__global__ void __launch_bounds__(128) joints_kernel(
    const float* __restrict__ Jreg,
    const float* __restrict__ shapedirs,
    const float* __restrict__ v_template,
    const float* __restrict__ beta)
{
    const int s = blockIdx.x;
    const int j = blockIdx.y;
    const int tid = threadIdx.x;

    const int v0 = s * JCHUNK;
    const int nv = min(JCHUNK, NV - v0);      // 128, or 106 on the last slice

    __shared__ float sb[10];
    __shared__ __align__(16) float s_sd[JCHUNK * 30];   // 15360 B, 16B-aligned
    __shared__ __align__(16) float s_vt[JCHUNK * 3];    // 1536 B
    if (tid < 10) sb[tid] = beta[tid];

    // coalesced stage: shapedirs chunk (nv*30 floats, always /4; global base
    // offset v0*30*4 = s*15360 bytes is a 16B multiple)
    {
        const int nf4 = (nv * 30) / 4;
        const float4* src4 = (const float4*)(shapedirs + (long long)v0 * 30);
        float4* dst4 = (float4*)s_sd;
        for (int i = tid; i < nf4; i += 128) dst4[i] = src4[i];
    }
    // coalesced stage: v_template chunk
    {
        const int nt = nv * 3;
        const float* srcv = v_template + (long long)v0 * 3;
        for (int i = tid; i < nt; i += 128) s_vt[i] = srcv[i];
    }
    __syncthreads();

    // one vertex per thread
    float accP0 = 0.f, accP1 = 0.f, accP2 = 0.f;
    float accD0 = 0.f, accD1 = 0.f, accD2 = 0.f;
    if (tid < nv) {
        float r = Jreg[j * NV + v0 + tid];
        const float* sd = &s_sd[tid * 30];    // (c,k) -> c*10 + k
        float d0 = 0.f, d1 = 0.f, d2 = 0.f;
        #pragma unroll
        for (int k = 0; k < 10; k++) {
            float b = sb[k];
            d0 += sd[k]      * b;
            d1 += sd[10 + k] * b;
            d2 += sd[20 + k] * b;
        }
        float t0 = s_vt[tid * 3 + 0];
        float t1 = s_vt[tid * 3 + 1];
        float t2 = s_vt[tid * 3 + 2];
        accD0 = r * t0;        accD1 = r * t1;        accD2 = r * t2;
        accP0 = r * (t0 + d0); accP1 = r * (t1 + d1); accP2 = r * (t2 + d2);
    }

    // warp shuffle reduction, then cross-warp via smem
    #pragma unroll
    for (int off = 16; off > 0; off >>= 1) {
        accP0 += __shfl_down_sync(0xffffffffu, accP0, off);
        accP1 += __shfl_down_sync(0xffffffffu, accP1, off);
        accP2 += __shfl_down_sync(0xffffffffu, accP2, off);
        accD0 += __shfl_down_sync(0xffffffffu, accD0, off);
        accD1 += __shfl_down_sync(0xffffffffu, accD1, off);
        accD2 += __shfl_down_sync(0xffffffffu, accD2, off);
    }
    __shared__ float wred[4][6];
    if ((tid & 31) == 0) {
        int w = tid >> 5;
        wred[w][0] = accP0; wred[w][1] = accP1; wred[w][2] = accP2;
        wred[w][3] = accD0; wred[w][4] = accD1; wred[w][5] = accD2;
    }
    __syncthreads();
    if (tid < 6)
        g_part[j][s][tid] = wred[0][tid] + wred[1][tid] + wred[2][tid] + wred[3][tid];
}

// ---------------------------------------------------------------------------
// Kernel 2: build the 24 blend transforms A_j = pose_j @ inv(da_j)
// ---------------------------------------------------------------------------
__device__ __forceinline__ void matmul4(const float* A, const float* B, float* C)
{
    #pragma unroll
    for (int r = 0; r < 4; r++)
        #pragma unroll
        for (int c = 0; c < 4; c++) {
            float s = 0.f;
            #pragma unroll
            for (int k = 0; k < 4; k++) s += A[r * 4 + k] * B[k * 4 + c];
            C[r * 4 + c] = s;
        }
}

__global__ void transforms_kernel(const float* __restrict__ theta,
                                  const float* __restrict__ da_theta)
{
    __shared__ float L[2][NJ][16];
    __shared__ float G[2][NJ][16];
    __shared__ float Jm[2][NJ][3];
    const int tid = threadIdx.x;

    // phase 0: reduce the per-slice partials -> joint locations
    if (tid < 48) {
        int w = tid / NJ;            // 0 = pose, 1 = da (rest)
        int j = tid % NJ;
        float a0 = 0.f, a1 = 0.f, a2 = 0.f;
        for (int s = 0; s < JSPLIT; s++) {
            a0 += g_part[j][s][w * 3 + 0];
            a1 += g_part[j][s][w * 3 + 1];
            a2 += g_part[j][s][w * 3 + 2];
        }
        Jm[w][j][0] = a0; Jm[w][j][1] = a1; Jm[w][j][2] = a2;
    }
    __syncthreads();

    // phase 1: rodrigues + local 4x4
    if (tid < 48) {
        int w = tid / NJ;
        int j = tid % NJ;
        const float* th = (w == 0) ? theta : da_theta;
        float r0 = th[j * 3 + 0], r1 = th[j * 3 + 1], r2 = th[j * 3 + 2];
        float n  = sqrtf(r0 * r0 + r1 * r1 + r2 * r2) + 1e-8f;
        float co = cosf(n), si = sinf(n);
        float u0 = r0 / n, u1 = r1 / n, u2 = r2 / n;
        float omc = 1.0f - co;

        float R00 = co + omc * u0 * u0;
        float R01 = omc * u0 * u1 - si * u2;
        float R02 = omc * u0 * u2 + si * u1;
        float R10 = omc * u1 * u0 + si * u2;
        float R11 = co + omc * u1 * u1;
        float R12 = omc * u1 * u2 - si * u0;
        float R20 = omc * u2 * u0 - si * u1;
        float R21 = omc * u2 * u1 + si * u0;
        float R22 = co + omc * u2 * u2;

        int p = c_par[j];
        float jr0, jr1, jr2;
        if (p < 0) { jr0 = Jm[w][j][0]; jr1 = Jm[w][j][1]; jr2 = Jm[w][j][2]; }
        else {
            jr0 = Jm[w][j][0] - Jm[w][p][0];
            jr1 = Jm[w][j][1] - Jm[w][p][1];
            jr2 = Jm[w][j][2] - Jm[w][p][2];
        }
        float* Lw = &L[w][j][0];
        Lw[0] = R00; Lw[1] = R01; Lw[2]  = R02; Lw[3]  = jr0;
        Lw[4] = R10; Lw[5] = R11; Lw[6]  = R12; Lw[7]  = jr1;
        Lw[8] = R20; Lw[9] = R21; Lw[10] = R22; Lw[11] = jr2;
        Lw[12] = 0.f; Lw[13] = 0.f; Lw[14] = 0.f; Lw[15] = 1.f;
    }
    __syncthreads();

    // phase 2: kinematic chain (two independent serial chains)
    if (tid < 2) {
        int w = tid;
        #pragma unroll
        for (int q = 0; q < 16; q++) G[w][0][q] = L[w][0][q];
        for (int i = 1; i < NJ; i++)
            matmul4(&G[w][c_par[i]][0], &L[w][i][0], &G[w][i][0]);
    }
    __syncthreads();

    // phase 3: pack + rigid inverse + A = pose' @ inv(da')
    if (tid < NJ) {
        int j = tid;
        float Rp[9], tp[3], Rd[9], td[3];
        #pragma unroll
        for (int r = 0; r < 3; r++) {
            #pragma unroll
            for (int c = 0; c < 3; c++) {
                Rp[r * 3 + c] = G[0][j][r * 4 + c];
                Rd[r * 3 + c] = G[1][j][r * 4 + c];
            }
            tp[r] = G[0][j][r * 4 + 3] - (Rp[r*3+0] * Jm[0][j][0] +
                                          Rp[r*3+1] * Jm[0][j][1] +
                                          Rp[r*3+2] * Jm[0][j][2]);
            td[r] = G[1][j][r * 4 + 3] - (Rd[r*3+0] * Jm[1][j][0] +
                                          Rd[r*3+1] * Jm[1][j][1] +
                                          Rd[r*3+2] * Jm[1][j][2]);
        }
        // rigid inverse: inv(da') = [Rd^T | -Rd^T td]; A_R = Rp Rd^T, A_t = tp - A_R td
        #pragma unroll
        for (int r = 0; r < 3; r++) {
            float a0 = Rp[r*3+0]*Rd[0] + Rp[r*3+1]*Rd[1] + Rp[r*3+2]*Rd[2];
            float a1 = Rp[r*3+0]*Rd[3] + Rp[r*3+1]*Rd[4] + Rp[r*3+2]*Rd[5];
            float a2 = Rp[r*3+0]*Rd[6] + Rp[r*3+1]*Rd[7] + Rp[r*3+2]*Rd[8];
            float at = tp[r] - (a0 * td[0] + a1 * td[1] + a2 * td[2]);
            g_A[j * 12 + r * 4 + 0] = a0;
            g_A[j * 12 + r * 4 + 1] = a1;
            g_A[j * 12 + r * 4 + 2] = a2;
            g_A[j * 12 + r * 4 + 3] = at;
        }
    }
}

// ---------------------------------------------------------------------------
// Kernel 3: LBS. 4 points/thread, f32x2 FMAs, smem LDS.128 coefficients,
// ld/st.global.cs.v2.u64, unroll 4 — now at 10 blocks/SM (51-reg cap).
// ---------------------------------------------------------------------------
__device__ __forceinline__ u64 pack2(float lo, float hi) {
    u64 d; asm("mov.b64 %0, {%1, %2};" : "=l"(d) : "f"(lo), "f"(hi)); return d;
}
__device__ __forceinline__ u64 fma2(u64 a, u64 b, u64 c) {
    u64 d; asm("fma.rn.f32x2 %0, %1, %2, %3;" : "=l"(d) : "l"(a), "l"(b), "l"(c));
    return d;
}
__device__ __forceinline__ void ldg128_cs(const void* p, u64& a, u64& b) {
    asm volatile("ld.global.cs.v2.u64 {%0, %1}, [%2];"
                 : "=l"(a), "=l"(b) : "l"(p));
}
__device__ __forceinline__ void stg128_cs(void* p, u64 a, u64 b) {
    asm volatile("st.global.cs.v2.u64 [%0], {%1, %2};"
                 :: "l"(p), "l"(a), "l"(b));
}

__global__ void __launch_bounds__(128, 10) lbs_kernel(const float* __restrict__ pts,
                                                      const float* __restrict__ wts,
                                                      float* __restrict__ out,
                                                      int N)
{
    // coefficients duplicated (a,a), packed two-per-16B for LDS.128 loads
    __shared__ __align__(16) ulonglong2 sA[NJ * 6];   // [j*6 + c*2 + h]
    for (int i = threadIdx.x; i < NJ * 6; i += blockDim.x) {
        float a0 = g_A[i * 2 + 0];
        float a1 = g_A[i * 2 + 1];
        ulonglong2 e;
        e.x = pack2(a0, a0);
        e.y = pack2(a1, a1);
        sA[i] = e;
    }
    __syncthreads();

    long long base = ((long long)blockIdx.x * blockDim.x + threadIdx.x) * 4;
    if (base >= N) return;

    if (base + 4 <= N) {
        u64 x01, x23, y01, y23, z01, z23;
        ldg128_cs(pts + base,                x01, x23);
        ldg128_cs(pts + (long long)N + base, y01, y23);
        ldg128_cs(pts + 2LL * N + base,      z01, z23);

        u64 o01[3], o23[3];
        #pragma unroll
        for (int c = 0; c < 3; c++) { o01[c] = 0ull; o23[c] = 0ull; }

        #pragma unroll 4
        for (int j = 0; j < NJ; j++) {
            u64 w01, w23;
            ldg128_cs(wts + (long long)j * N + base, w01, w23);
            #pragma unroll
            for (int c = 0; c < 3; c++) {
                ulonglong2 q0 = sA[j * 6 + c * 2 + 0];   // (a0,a0),(a1,a1)
                ulonglong2 q1 = sA[j * 6 + c * 2 + 1];   // (a2,a2),(a3,a3)
                u64 r01 = fma2(q0.x, x01, fma2(q0.y, y01, fma2(q1.x, z01, q1.y)));
                u64 r23 = fma2(q0.x, x23, fma2(q0.y, y23, fma2(q1.x, z23, q1.y)));
                o01[c] = fma2(w01, r01, o01[c]);
                o23[c] = fma2(w23, r23, o23[c]);
            }
        }

        #pragma unroll
        for (int c = 0; c < 3; c++)
            stg128_cs(out + (long long)c * N + base, o01[c], o23[c]);
    } else {
        // scalar tail (never taken for N % 4 == 0)
        for (long long n = base; n < N; n++) {
            float x = pts[n], y = pts[(long long)N + n], z = pts[2LL * N + n];
            float o0 = 0.f, o1 = 0.f, o2 = 0.f;
            for (int j = 0; j < NJ; j++) {
                float w = wts[(long long)j * N + n];
                const float* A = &g_A[j * 12];
                o0 += w * (A[0] * x + A[1] * y + A[2]  * z + A[3]);
                o1 += w * (A[4] * x + A[5] * y + A[6]  * z + A[7]);
                o2 += w * (A[8] * x + A[9] * y + A[10] * z + A[11]);
            }
            out[n] = o0;
            out[(long long)N + n] = o1;
            out[2LL * N + n] = o2;
        }
    }
}

// ---------------------------------------------------------------------------
extern "C" void kernel_launch(void* const* d_in, const int* in_sizes, int n_in,
                              void* d_out, int out_size)
{
    const float* pts       = (const float*)d_in[0];  // (3, N)
    const float* wts       = (const float*)d_in[1];  // (24, N)
    const float* beta      = (const float*)d_in[2];  // (10,)
    const float* theta     = (const float*)d_in[3];  // (24, 3)
    const float* da_theta  = (const float*)d_in[4];  // (24, 3)
    const float* shapedirs = (const float*)d_in[5];  // (6890, 3, 10)
    const float* v_templ   = (const float*)d_in[6];  // (6890, 3)
    const float* Jreg      = (const float*)d_in[7];  // (24, 6890)
    float* out = (float*)d_out;                      // (1, 3, N)

    const int N = in_sizes[0] / 3;

    dim3 jgrid(JSPLIT, NJ);
    joints_kernel<<<jgrid, 128>>>(Jreg, shapedirs, v_templ, beta);
    transforms_kernel<<<1, 64>>>(theta, da_theta);

    long long nthreads = ((long long)N + 3) / 4;
    int blocks = (int)((nthreads + 127) / 128);
    lbs_kernel<<<blocks, 128>>>(pts, wts, out, N);
}

// round 13
// speedup vs baseline: 1.1513x; 1.1513x over previous
#include <cuda_runtime.h>

#define NJ 24
#define NV 6890
#define JSPLIT 54
#define JCHUNK 128   // 54*128 = 6912 >= 6890

__device__ __constant__ int c_par[NJ] =
    {-1,0,0,0,1,2,3,4,5,6,7,8,9,9,9,12,13,14,16,17,18,19,20,21};

typedef unsigned long long u64;

// scratch (no allocations allowed -> __device__ globals)
__device__ float g_part[NJ][JSPLIT][6];  // per-(joint,slice) partial sums
__device__ float g_A[NJ * 12];           // per joint: 3x4 row-major blend matrix

__device__ __forceinline__ void gdc_launch_dependents() {
    asm volatile("griddepcontrol.launch_dependents;");
}
__device__ __forceinline__ void gdc_wait() {
    asm volatile("griddepcontrol.wait;" ::: "memory");
}

// ---------------------------------------------------------------------------
// Kernel 1: partial joint sums.  grid = (JSPLIT, NJ), block = 128.
// ---------------------------------------------------------------------------
__global__ void __launch_bounds__(128) joints_kernel(
    const float* __restrict__ Jreg,
    const float* __restrict__ shapedirs,
    const float* __restrict__ v_template,
    const float* __restrict__ beta)
{
    const int s = blockIdx.x;
    const int j = blockIdx.y;
    const int tid = threadIdx.x;

    const int v0 = s * JCHUNK;
    const int nv = min(JCHUNK, NV - v0);      // 128, or 106 on the last slice

    __shared__ float sb[10];
    __shared__ __align__(16) float s_sd[JCHUNK * 30];   // 15360 B
    __shared__ __align__(16) float s_vt[JCHUNK * 3];
    if (tid < 10) sb[tid] = beta[tid];

    {
        const int nf4 = (nv * 30) / 4;
        const float4* src4 = (const float4*)(shapedirs + (long long)v0 * 30);
        float4* dst4 = (float4*)s_sd;
        for (int i = tid; i < nf4; i += 128) dst4[i] = src4[i];
    }
    {
        const int nt = nv * 3;
        const float* srcv = v_template + (long long)v0 * 3;
        for (int i = tid; i < nt; i += 128) s_vt[i] = srcv[i];
    }
    __syncthreads();

    float accP0 = 0.f, accP1 = 0.f, accP2 = 0.f;
    float accD0 = 0.f, accD1 = 0.f, accD2 = 0.f;
    if (tid < nv) {
        float r = Jreg[j * NV + v0 + tid];
        const float* sd = &s_sd[tid * 30];
        float d0 = 0.f, d1 = 0.f, d2 = 0.f;
        #pragma unroll
        for (int k = 0; k < 10; k++) {
            float b = sb[k];
            d0 += sd[k]      * b;
            d1 += sd[10 + k] * b;
            d2 += sd[20 + k] * b;
        }
        float t0 = s_vt[tid * 3 + 0];
        float t1 = s_vt[tid * 3 + 1];
        float t2 = s_vt[tid * 3 + 2];
        accD0 = r * t0;        accD1 = r * t1;        accD2 = r * t2;
        accP0 = r * (t0 + d0); accP1 = r * (t1 + d1); accP2 = r * (t2 + d2);
    }

    #pragma unroll
    for (int off = 16; off > 0; off >>= 1) {
        accP0 += __shfl_down_sync(0xffffffffu, accP0, off);
        accP1 += __shfl_down_sync(0xffffffffu, accP1, off);
        accP2 += __shfl_down_sync(0xffffffffu, accP2, off);
        accD0 += __shfl_down_sync(0xffffffffu, accD0, off);
        accD1 += __shfl_down_sync(0xffffffffu, accD1, off);
        accD2 += __shfl_down_sync(0xffffffffu, accD2, off);
    }
    __shared__ float wred[4][6];
    if ((tid & 31) == 0) {
        int w = tid >> 5;
        wred[w][0] = accP0; wred[w][1] = accP1; wred[w][2] = accP2;
        wred[w][3] = accD0; wred[w][4] = accD1; wred[w][5] = accD2;
    }
    __syncthreads();
    if (tid < 6)
        g_part[j][s][tid] = wred[0][tid] + wred[1][tid] + wred[2][tid] + wred[3][tid];

    // results written -> let the transforms kernel begin launching
    __threadfence();
    __syncthreads();
    if (tid == 0) gdc_launch_dependents();
}

// ---------------------------------------------------------------------------
// Kernel 2: build the 24 blend transforms A_j = pose_j @ inv(da_j)
// (PDL: launched while joints still runs; waits for its results at entry)
// ---------------------------------------------------------------------------
__device__ __forceinline__ void matmul4(const float* A, const float* B, float* C)
{
    #pragma unroll
    for (int r = 0; r < 4; r++)
        #pragma unroll
        for (int c = 0; c < 4; c++) {
            float s = 0.f;
            #pragma unroll
            for (int k = 0; k < 4; k++) s += A[r * 4 + k] * B[k * 4 + c];
            C[r * 4 + c] = s;
        }
}

__global__ void transforms_kernel(const float* __restrict__ theta,
                                  const float* __restrict__ da_theta)
{
    __shared__ float L[2][NJ][16];
    __shared__ float G[2][NJ][16];
    __shared__ float Jm[2][NJ][3];
    const int tid = threadIdx.x;

    gdc_wait();   // joints results must be visible

    // phase 0: reduce the per-slice partials -> joint locations
    if (tid < 48) {
        int w = tid / NJ;            // 0 = pose, 1 = da (rest)
        int j = tid % NJ;
        float a0 = 0.f, a1 = 0.f, a2 = 0.f;
        for (int s = 0; s < JSPLIT; s++) {
            a0 += g_part[j][s][w * 3 + 0];
            a1 += g_part[j][s][w * 3 + 1];
            a2 += g_part[j][s][w * 3 + 2];
        }
        Jm[w][j][0] = a0; Jm[w][j][1] = a1; Jm[w][j][2] = a2;
    }
    __syncthreads();

    // phase 1: rodrigues + local 4x4
    if (tid < 48) {
        int w = tid / NJ;
        int j = tid % NJ;
        const float* th = (w == 0) ? theta : da_theta;
        float r0 = th[j * 3 + 0], r1 = th[j * 3 + 1], r2 = th[j * 3 + 2];
        float n  = sqrtf(r0 * r0 + r1 * r1 + r2 * r2) + 1e-8f;
        float co = cosf(n), si = sinf(n);
        float u0 = r0 / n, u1 = r1 / n, u2 = r2 / n;
        float omc = 1.0f - co;

        float R00 = co + omc * u0 * u0;
        float R01 = omc * u0 * u1 - si * u2;
        float R02 = omc * u0 * u2 + si * u1;
        float R10 = omc * u1 * u0 + si * u2;
        float R11 = co + omc * u1 * u1;
        float R12 = omc * u1 * u2 - si * u0;
        float R20 = omc * u2 * u0 - si * u1;
        float R21 = omc * u2 * u1 + si * u0;
        float R22 = co + omc * u2 * u2;

        int p = c_par[j];
        float jr0, jr1, jr2;
        if (p < 0) { jr0 = Jm[w][j][0]; jr1 = Jm[w][j][1]; jr2 = Jm[w][j][2]; }
        else {
            jr0 = Jm[w][j][0] - Jm[w][p][0];
            jr1 = Jm[w][j][1] - Jm[w][p][1];
            jr2 = Jm[w][j][2] - Jm[w][p][2];
        }
        float* Lw = &L[w][j][0];
        Lw[0] = R00; Lw[1] = R01; Lw[2]  = R02; Lw[3]  = jr0;
        Lw[4] = R10; Lw[5] = R11; Lw[6]  = R12; Lw[7]  = jr1;
        Lw[8] = R20; Lw[9] = R21; Lw[10] = R22; Lw[11] = jr2;
        Lw[12] = 0.f; Lw[13] = 0.f; Lw[14] = 0.f; Lw[15] = 1.f;
    }
    __syncthreads();

    // phase 2: kinematic chain
    if (tid < 2) {
        int w = tid;
        #pragma unroll
        for (int q = 0; q < 16; q++) G[w][0][q] = L[w][0][q];
        for (int i = 1; i < NJ; i++)
            matmul4(&G[w][c_par[i]][0], &L[w][i][0], &G[w][i][0]);
    }
    __syncthreads();

    // phase 3: pack + rigid inverse + A = pose' @ inv(da')
    if (tid < NJ) {
        int j = tid;
        float Rp[9], tp[3], Rd[9], td[3];
        #pragma unroll
        for (int r = 0; r < 3; r++) {
            #pragma unroll
            for (int c = 0; c < 3; c++) {
                Rp[r * 3 + c] = G[0][j][r * 4 + c];
                Rd[r * 3 + c] = G[1][j][r * 4 + c];
            }
            tp[r] = G[0][j][r * 4 + 3] - (Rp[r*3+0] * Jm[0][j][0] +
                                          Rp[r*3+1] * Jm[0][j][1] +
                                          Rp[r*3+2] * Jm[0][j][2]);
            td[r] = G[1][j][r * 4 + 3] - (Rd[r*3+0] * Jm[1][j][0] +
                                          Rd[r*3+1] * Jm[1][j][1] +
                                          Rd[r*3+2] * Jm[1][j][2]);
        }
        #pragma unroll
        for (int r = 0; r < 3; r++) {
            float a0 = Rp[r*3+0]*Rd[0] + Rp[r*3+1]*Rd[1] + Rp[r*3+2]*Rd[2];
            float a1 = Rp[r*3+0]*Rd[3] + Rp[r*3+1]*Rd[4] + Rp[r*3+2]*Rd[5];
            float a2 = Rp[r*3+0]*Rd[6] + Rp[r*3+1]*Rd[7] + Rp[r*3+2]*Rd[8];
            float at = tp[r] - (a0 * td[0] + a1 * td[1] + a2 * td[2]);
            g_A[j * 12 + r * 4 + 0] = a0;
            g_A[j * 12 + r * 4 + 1] = a1;
            g_A[j * 12 + r * 4 + 2] = a2;
            g_A[j * 12 + r * 4 + 3] = at;
        }
    }

    __threadfence();
    __syncthreads();
    if (tid == 0) gdc_launch_dependents();
}

// ---------------------------------------------------------------------------
// Kernel 3: LBS (R10-best SASS; PDL: point loads issued pre-sync).
// ---------------------------------------------------------------------------
__device__ __forceinline__ u64 pack2(float lo, float hi) {
    u64 d; asm("mov.b64 %0, {%1, %2};" : "=l"(d) : "f"(lo), "f"(hi)); return d;
}
__device__ __forceinline__ u64 fma2(u64 a, u64 b, u64 c) {
    u64 d; asm("fma.rn.f32x2 %0, %1, %2, %3;" : "=l"(d) : "l"(a), "l"(b), "l"(c));
    return d;
}
__device__ __forceinline__ void ldg128_cs(const void* p, u64& a, u64& b) {
    asm volatile("ld.global.cs.v2.u64 {%0, %1}, [%2];"
                 : "=l"(a), "=l"(b) : "l"(p));
}
__device__ __forceinline__ void stg128_cs(void* p, u64 a, u64 b) {
    asm volatile("st.global.cs.v2.u64 [%0], {%1, %2};"
                 :: "l"(p), "l"(a), "l"(b));
}

__global__ void __launch_bounds__(128, 8) lbs_kernel(const float* __restrict__ pts,
                                                     const float* __restrict__ wts,
                                                     float* __restrict__ out,
                                                     int N)
{
    __shared__ __align__(16) ulonglong2 sA[NJ * 6];

    long long base = ((long long)blockIdx.x * blockDim.x + threadIdx.x) * 4;
    const bool full = (base + 4 <= N);

    // pre-sync: start the point loads (independent of g_A)
    u64 x01 = 0, x23 = 0, y01 = 0, y23 = 0, z01 = 0, z23 = 0;
    if (full) {
        ldg128_cs(pts + base,                x01, x23);
        ldg128_cs(pts + (long long)N + base, y01, y23);
        ldg128_cs(pts + 2LL * N + base,      z01, z23);
    }

    gdc_wait();   // g_A must be visible before staging sA

    for (int i = threadIdx.x; i < NJ * 6; i += blockDim.x) {
        float a0 = g_A[i * 2 + 0];
        float a1 = g_A[i * 2 + 1];
        ulonglong2 e;
        e.x = pack2(a0, a0);
        e.y = pack2(a1, a1);
        sA[i] = e;
    }
    __syncthreads();

    if (base >= N) return;

    if (full) {
        u64 o01[3], o23[3];
        #pragma unroll
        for (int c = 0; c < 3; c++) { o01[c] = 0ull; o23[c] = 0ull; }

        #pragma unroll 4
        for (int j = 0; j < NJ; j++) {
            u64 w01, w23;
            ldg128_cs(wts + (long long)j * N + base, w01, w23);
            #pragma unroll
            for (int c = 0; c < 3; c++) {
                ulonglong2 q0 = sA[j * 6 + c * 2 + 0];
                ulonglong2 q1 = sA[j * 6 + c * 2 + 1];
                u64 r01 = fma2(q0.x, x01, fma2(q0.y, y01, fma2(q1.x, z01, q1.y)));
                u64 r23 = fma2(q0.x, x23, fma2(q0.y, y23, fma2(q1.x, z23, q1.y)));
                o01[c] = fma2(w01, r01, o01[c]);
                o23[c] = fma2(w23, r23, o23[c]);
            }
        }

        #pragma unroll
        for (int c = 0; c < 3; c++)
            stg128_cs(out + (long long)c * N + base, o01[c], o23[c]);
    } else {
        for (long long n = base; n < N; n++) {
            float x = pts[n], y = pts[(long long)N + n], z = pts[2LL * N + n];
            float o0 = 0.f, o1 = 0.f, o2 = 0.f;
            for (int j = 0; j < NJ; j++) {
                float w = wts[(long long)j * N + n];
                const float* A = &g_A[j * 12];
                o0 += w * (A[0] * x + A[1] * y + A[2]  * z + A[3]);
                o1 += w * (A[4] * x + A[5] * y + A[6]  * z + A[7]);
                o2 += w * (A[8] * x + A[9] * y + A[10] * z + A[11]);
            }
            out[n] = o0;
            out[(long long)N + n] = o1;
            out[2LL * N + n] = o2;
        }
    }
}

// ---------------------------------------------------------------------------
extern "C" void kernel_launch(void* const* d_in, const int* in_sizes, int n_in,
                              void* d_out, int out_size)
{
    const float* pts       = (const float*)d_in[0];  // (3, N)
    const float* wts       = (const float*)d_in[1];  // (24, N)
    const float* beta      = (const float*)d_in[2];  // (10,)
    const float* theta     = (const float*)d_in[3];  // (24, 3)
    const float* da_theta  = (const float*)d_in[4];  // (24, 3)
    const float* shapedirs = (const float*)d_in[5];  // (6890, 3, 10)
    const float* v_templ   = (const float*)d_in[6];  // (6890, 3)
    const float* Jreg      = (const float*)d_in[7];  // (24, 6890)
    float* out = (float*)d_out;                      // (1, 3, N)

    const int N = in_sizes[0] / 3;

    // kernel 1: plain launch
    dim3 jgrid(JSPLIT, NJ);
    joints_kernel<<<jgrid, 128>>>(Jreg, shapedirs, v_templ, beta);

    // kernel 2: PDL-launched (overlaps launch with joints execution)
    cudaLaunchAttribute attr[1];
    attr[0].id = cudaLaunchAttributeProgrammaticStreamSerialization;
    attr[0].val.programmaticStreamSerializationAllowed = 1;

    {
        cudaLaunchConfig_t cfg = {};
        cfg.gridDim = dim3(1, 1, 1);
        cfg.blockDim = dim3(64, 1, 1);
        cfg.dynamicSmemBytes = 0;
        cfg.stream = 0;
        cfg.attrs = attr;
        cfg.numAttrs = 1;
        cudaLaunchKernelEx(&cfg, transforms_kernel, theta, da_theta);
    }

    // kernel 3: PDL-launched (points prefetch overlaps transforms)
    {
        long long nthreads = ((long long)N + 3) / 4;
        int blocks = (int)((nthreads + 127) / 128);
        cudaLaunchConfig_t cfg = {};
        cfg.gridDim = dim3(blocks, 1, 1);
        cfg.blockDim = dim3(128, 1, 1);
        cfg.dynamicSmemBytes = 0;
        cfg.stream = 0;
        cfg.attrs = attr;
        cfg.numAttrs = 1;
        cudaLaunchKernelEx(&cfg, lbs_kernel, pts, wts, out, N);
    }
}